// round 9
// baseline (speedup 1.0000x reference)
#include <cuda_runtime.h>
#include <math.h>

#define Bv 32
#define Sv 2048
#define Ev 1024
#define Dv 1024

// Scratch (no device allocations, no atomics)
__device__ float g_pp [Bv * 128];          // hp partials per (batch, itile)
__device__ float g_qp4[4][Bv * Ev];        // q partials: 4 d-chunks
__device__ float g_c  [Bv];
__device__ float g_att[Bv * Sv];

__device__ __forceinline__ float warp_sum(float v) {
#pragma unroll
    for (int o = 16; o > 0; o >>= 1) v += __shfl_xor_sync(0xffffffffu, v, o);
    return v;
}
__device__ __forceinline__ float warp_max(float v) {
#pragma unroll
    for (int o = 16; o > 0; o >>= 1) v = fmaxf(v, __shfl_xor_sync(0xffffffffu, v, o));
    return v;
}

// ---------------------------------------------------------------------------
// k_hp (side stream): warp per i, 8 batches per block, 512 blocks.
// Partial vp·tanh(Wp h + b) sums per (b, itile) -> g_pp. Consumed by k_fin only.
// ---------------------------------------------------------------------------
__global__ void __launch_bounds__(256) k_hp(const float* __restrict__ h,
                     const float* __restrict__ Wp_w,
                     const float* __restrict__ Wp_b,
                     const float* __restrict__ vp_w) {
    __shared__ float4 hs4[8][Dv / 4];     // 32 KB
    __shared__ float wtmp[8][8];
    int t = threadIdx.x;
    int b0 = (blockIdx.x >> 7) * 8;
    int itile = blockIdx.x & 127;
    for (int idx = t; idx < 8 * (Dv / 4); idx += 256) {
        int k = idx >> 8, j = idx & 255;
        hs4[k][j] = ((const float4*)(h + (size_t)(b0 + k) * Dv))[j];
    }
    __syncthreads();
    int w = t >> 5, lane = t & 31;
    int i = itile * 8 + w;
    const float4* wr = (const float4*)(Wp_w + (size_t)i * Dv);
    float acc[8];
#pragma unroll
    for (int k = 0; k < 8; k++) acc[k] = 0.f;
#pragma unroll
    for (int j = lane; j < Dv / 4; j += 32) {
        float4 wv = wr[j];
#pragma unroll
        for (int k = 0; k < 8; k++) {
            float4 x = hs4[k][j];
            acc[k] += wv.x * x.x + wv.y * x.y + wv.z * x.z + wv.w * x.w;
        }
    }
#pragma unroll
    for (int k = 0; k < 8; k++) acc[k] = warp_sum(acc[k]);
    if (lane == 0) {
        float bia = Wp_b[i];
        float vp  = vp_w[i];
#pragma unroll
        for (int k = 0; k < 8; k++) wtmp[w][k] = tanhf(acc[k] + bia) * vp;
    }
    __syncthreads();
    if (t < 8) {
        float s = 0.f;
#pragma unroll
        for (int w2 = 0; w2 < 8; w2++) s += wtmp[w2][t];
        g_pp[(b0 + t) * 128 + itile] = s;
    }
}

// ---------------------------------------------------------------------------
// k_q (main stream): 160 blocks.
//   [0,128): q partials. (e-tile 128) x (d-chunk 256) x (8 batches) -> g_qp4.
//   [128,160): c[b] = h[b]·Wa_b.
// ---------------------------------------------------------------------------
__global__ void __launch_bounds__(256) k_q(const float* __restrict__ h,
                    const float* __restrict__ Wa_w,
                    const float* __restrict__ Wa_b) {
    __shared__ float4 sbuf[2560];          // 40 KB
    int bid = blockIdx.x, t = threadIdx.x;
    if (bid < 128) {
        int et = bid & 7;                  // e-tile of 128 floats
        int dc = (bid >> 3) & 3;           // d-chunk of 256 rows
        int bg = bid >> 5;                 // 4 groups of 8 batches
        int b0 = bg * 8, d0 = dc * 256, e0 = et * 128;
        float*  hs  = (float*)sbuf;        // [8][256] = 8 KB
        float4* red = sbuf + 512;          // [8 dg][8 k][32 col] = 32 KB
        for (int idx = t; idx < 8 * 256; idx += 256) {
            int k = idx >> 8, d = idx & 255;
            hs[k * 256 + d] = h[(size_t)(b0 + k) * Dv + d0 + d];
        }
        __syncthreads();
        int col = t & 31, dg = t >> 5;     // 8 d-groups of 32 rows
        float4 acc[8];
#pragma unroll
        for (int k = 0; k < 8; k++) acc[k] = make_float4(0.f, 0.f, 0.f, 0.f);
#pragma unroll 4
        for (int i = 0; i < 32; i++) {
            int d = dg * 32 + i;
            float4 wv = ((const float4*)(Wa_w + (size_t)(d0 + d) * Ev + e0))[col];
#pragma unroll
            for (int k = 0; k < 8; k++) {
                float x = hs[k * 256 + d];
                acc[k].x += wv.x * x; acc[k].y += wv.y * x;
                acc[k].z += wv.z * x; acc[k].w += wv.w * x;
            }
        }
#pragma unroll
        for (int k = 0; k < 8; k++) red[(dg * 8 + k) * 32 + col] = acc[k];
        __syncthreads();
#pragma unroll
        for (int o = 4; o > 0; o >>= 1) {
            if (dg < o) {
#pragma unroll
                for (int k = 0; k < 8; k++) {
                    float4 u = red[(dg * 8 + k) * 32 + col];
                    float4 v = red[((dg + o) * 8 + k) * 32 + col];
                    u.x += v.x; u.y += v.y; u.z += v.z; u.w += v.w;
                    red[(dg * 8 + k) * 32 + col] = u;
                }
            }
            __syncthreads();
        }
        if (dg == 0) {
#pragma unroll
            for (int k = 0; k < 8; k++)
                ((float4*)(g_qp4[dc] + (size_t)(b0 + k) * Ev + e0))[col] =
                    red[k * 32 + col];
        }
    } else {
        int b = bid - 128;
        float v = 0.f;
        for (int d = t; d < Dv; d += 256) v += h[b * Dv + d] * Wa_b[d];
        v = warp_sum(v);
        __shared__ float redc[8];
        if ((t & 31) == 0) redc[t >> 5] = v;
        __syncthreads();
        if (t == 0) {
            float s = 0.f;
#pragma unroll
            for (int i = 0; i < 8; i++) s += redc[i];
            g_c[b] = s;
        }
    }
}

// ---------------------------------------------------------------------------
// k_att: grid (32 tiles, 32 batches), 256 threads. Cheap 4-partial q reduce,
// then att for 64 s rows (2 rows per warp-iteration, streaming loads).
// ---------------------------------------------------------------------------
__global__ void __launch_bounds__(256) k_att(const float* __restrict__ enc) {
    __shared__ float4 qs[Ev / 4];
    int tile = blockIdx.x, b = blockIdx.y, t = threadIdx.x;

    {   // q = sum of 4 d-chunk partials: one float4 per thread
        float4 s0 = ((const float4*)(g_qp4[0] + b * Ev))[t];
        float4 s1 = ((const float4*)(g_qp4[1] + b * Ev))[t];
        float4 s2 = ((const float4*)(g_qp4[2] + b * Ev))[t];
        float4 s3 = ((const float4*)(g_qp4[3] + b * Ev))[t];
        float4 r;
        r.x = (s0.x + s1.x) + (s2.x + s3.x);
        r.y = (s0.y + s1.y) + (s2.y + s3.y);
        r.z = (s0.z + s1.z) + (s2.z + s3.z);
        r.w = (s0.w + s1.w) + (s2.w + s3.w);
        qs[t] = r;
    }
    __syncthreads();

    int w = t >> 5, lane = t & 31;
    float c = g_c[b];
#pragma unroll
    for (int r = 0; r < 8; r += 2) {
        int s = tile * 64 + w * 8 + r;
        const float4* er0 = (const float4*)(enc + ((size_t)b * Sv + s)     * Ev);
        const float4* er1 = (const float4*)(enc + ((size_t)b * Sv + s + 1) * Ev);
        float acc0 = 0.f, acc1 = 0.f;
#pragma unroll
        for (int j = lane; j < Ev / 4; j += 32) {
            float4 x  = qs[j];
            float4 a0 = __ldcs(er0 + j);
            float4 a1 = __ldcs(er1 + j);
            acc0 += a0.x * x.x + a0.y * x.y + a0.z * x.z + a0.w * x.w;
            acc1 += a1.x * x.x + a1.y * x.y + a1.z * x.z + a1.w * x.w;
        }
        acc0 = warp_sum(acc0);
        acc1 = warp_sum(acc1);
        if (lane == 0) {
            g_att[b * Sv + s]     = acc0 + c;
            g_att[b * Sv + s + 1] = acc1 + c;
        }
    }
}

// ---------------------------------------------------------------------------
// k_fin: grid (8 e-tiles, 32 batches), 1024 threads.
//   p from g_pp + softmax stats (redundant per tile, L2-hot); tile 0 writes
//   alpha; each block computes a 128-col slice of awe over a 64-row window
//   (branchless — gauss is exactly 0 outside, identical to the reference).
// ---------------------------------------------------------------------------
__global__ void k_fin(const float* __restrict__ enc, float* __restrict__ awe,
                      float* __restrict__ alpha, const float* __restrict__ vp_b) {
    int tile = blockIdx.x, b = blockIdx.y, t = threadIdx.x;
    int lane = t & 31, wrp = t >> 5;
    __shared__ float red[128];
    __shared__ float fin, shp;
    __shared__ float aw[64];
    __shared__ float4 pacc[32][32];        // 16 KB

    // p[b] from 128 hp partials
    if (t < 128) red[t] = g_pp[b * 128 + t];
    __syncthreads();
    for (int o = 64; o > 0; o >>= 1) {
        if (t < o) red[t] += red[t + o];
        __syncthreads();
    }
    if (t == 0) {
        float x = red[0] + vp_b[0];
        shp = (float)Sv / (1.f + expf(-x));
    }
    __syncthreads();
    float p = shp;
    int lo = (int)floorf(p) - 31;
    if (lo < 0) lo = 0;
    if (lo > Sv - 64) lo = Sv - 64;

    // softmax stats
    float a0 = g_att[b * Sv + t];
    float a1 = g_att[b * Sv + t + 1024];
    float m = warp_max(fmaxf(a0, a1));
    if (lane == 0) red[wrp] = m;
    __syncthreads();
    if (wrp == 0) {
        float v = warp_max(red[lane]);
        if (lane == 0) fin = v;
    }
    __syncthreads();
    float mb = fin;
    float e0 = expf(a0 - mb), e1 = expf(a1 - mb);
    float l = warp_sum(e0 + e1);
    __syncthreads();
    if (lane == 0) red[wrp] = l;
    __syncthreads();
    if (wrp == 0) {
        float v = warp_sum(red[lane]);
        if (lane == 0) fin = v;
    }
    __syncthreads();
    float inv = 1.f / fin;
    float d0 = (float)t - p, d1 = (float)(t + 1024) - p;
    float al0 = e0 * inv * expf(-d0 * d0 * 0.125f);
    float al1 = e1 * inv * expf(-d1 * d1 * 0.125f);
    if (tile == 0) {
        alpha[b * Sv + t]        = al0;
        alpha[b * Sv + t + 1024] = al1;
    }
    int w0 = t - lo, w1 = t + 1024 - lo;
    if ((unsigned)w0 < 64u) aw[w0] = al0;
    if ((unsigned)w1 < 64u) aw[w1] = al1;
    __syncthreads();

    // windowed awe slice: 64 rows x 128 cols, branchless
    int col = t & 31;
    int rg  = t >> 5;                      // 32 row-groups of 2 rows
    const float4* base = (const float4*)(enc + ((size_t)b * Sv + lo) * Ev)
                         + tile * 32;
    float4 acc = make_float4(0.f, 0.f, 0.f, 0.f);
#pragma unroll
    for (int i = 0; i < 2; i++) {
        int sl = rg * 2 + i;
        float a = aw[sl];
        float4 v = base[(size_t)sl * (Ev / 4) + col];
        acc.x += v.x * a; acc.y += v.y * a; acc.z += v.z * a; acc.w += v.w * a;
    }
    pacc[rg][col] = acc;
    __syncthreads();
#pragma unroll
    for (int o = 16; o > 0; o >>= 1) {
        if (rg < o) {
            float4 u = pacc[rg][col], v = pacc[rg + o][col];
            u.x += v.x; u.y += v.y; u.z += v.z; u.w += v.w;
            pacc[rg][col] = u;
        }
        __syncthreads();
    }
    if (t < 32)
        ((float4*)(awe + b * Ev + tile * 128))[t] = pacc[0][t];
}

extern "C" void kernel_launch(void* const* d_in, const int* in_sizes, int n_in,
                              void* d_out, int out_size) {
    const float* enc  = (const float*)d_in[0];   // [B,S,E]
    const float* h    = (const float*)d_in[1];   // [B,D]
    const float* Wa_w = (const float*)d_in[3];   // [D,E]
    const float* Wa_b = (const float*)d_in[4];   // [D]
    const float* Wp_w = (const float*)d_in[5];   // [D,D]
    const float* Wp_b = (const float*)d_in[6];   // [D]
    const float* vp_w = (const float*)d_in[7];   // [1,D]
    const float* vp_b = (const float*)d_in[8];   // [1]

    float* awe   = (float*)d_out;                 // [B,E]
    float* alpha = (float*)d_out + Bv * Ev;       // [B,S]

    // Fork: k_hp on side stream (compute-heavy, zero DRAM pressure) hides
    // under k_q -> k_att (DRAM-bound). Join before k_fin (sole g_pp consumer).
    cudaStream_t s1;
    cudaStreamCreateWithFlags(&s1, cudaStreamNonBlocking);
    cudaEvent_t evFork, evJoin;
    cudaEventCreateWithFlags(&evFork, cudaEventDisableTiming);
    cudaEventCreateWithFlags(&evJoin, cudaEventDisableTiming);

    cudaEventRecord(evFork, 0);
    cudaStreamWaitEvent(s1, evFork, 0);

    k_hp<<<512, 256, 0, s1>>>(h, Wp_w, Wp_b, vp_w);   // side stream

    k_q  <<<160, 256>>>(h, Wa_w, Wa_b);               // main stream
    k_att<<<dim3(32, Bv), 256>>>(enc);

    cudaEventRecord(evJoin, s1);
    cudaStreamWaitEvent(0, evJoin, 0);

    k_fin<<<dim3(8, Bv), 1024>>>(enc, awe, alpha, vp_b);
}

// round 10
// speedup vs baseline: 1.0385x; 1.0385x over previous
#include <cuda_runtime.h>
#include <math.h>

#define Bv 32
#define Sv 2048
#define Ev 1024
#define Dv 1024

// Scratch (no device allocations, no atomics)
__device__ float g_pp [Bv * 32];           // hp partials per (batch, itile32)
__device__ float g_qp4[4][Bv * Ev];        // q partials: 4 d-chunks
__device__ float g_c  [Bv];
__device__ float g_p  [Bv];
__device__ float g_att[Bv * Sv];

__device__ __forceinline__ float warp_sum(float v) {
#pragma unroll
    for (int o = 16; o > 0; o >>= 1) v += __shfl_xor_sync(0xffffffffu, v, o);
    return v;
}
__device__ __forceinline__ float warp_max(float v) {
#pragma unroll
    for (int o = 16; o > 0; o >>= 1) v = fmaxf(v, __shfl_xor_sync(0xffffffffu, v, o));
    return v;
}

// ---------------------------------------------------------------------------
// k_hp: 128 blocks x 1024 threads, single wave.
//   block = (batch-group of 8) x (i-tile of 32). Warp w owns i = itile*32+w
//   for all 8 batches; 32 warps share one 32 KB h tile. In-block reduce over
//   warps -> g_pp[(b,itile)] (32 partials per batch).
// ---------------------------------------------------------------------------
__global__ void __launch_bounds__(1024) k_hp(const float* __restrict__ h,
                     const float* __restrict__ Wp_w,
                     const float* __restrict__ Wp_b,
                     const float* __restrict__ vp_w) {
    __shared__ float4 hs4[8][Dv / 4];     // 32 KB
    __shared__ float wtmp[32][8];         // [warp][batch]
    int t = threadIdx.x;
    int bg = blockIdx.x >> 5;             // 4 batch groups
    int itile = blockIdx.x & 31;          // 32 i-tiles
    int b0 = bg * 8;
    {   // load 8 h rows: 2048 float4 / 1024 threads = 2 each
        int idx = t;
        hs4[idx >> 8][idx & 255] = ((const float4*)(h + (size_t)(b0 + (idx >> 8)) * Dv))[idx & 255];
        idx = t + 1024;
        hs4[idx >> 8][idx & 255] = ((const float4*)(h + (size_t)(b0 + (idx >> 8)) * Dv))[idx & 255];
    }
    __syncthreads();
    int w = t >> 5, lane = t & 31;
    int i = itile * 32 + w;
    const float4* wr = (const float4*)(Wp_w + (size_t)i * Dv);
    float acc[8];
#pragma unroll
    for (int k = 0; k < 8; k++) acc[k] = 0.f;
#pragma unroll
    for (int j = lane; j < Dv / 4; j += 32) {
        float4 wv = wr[j];
#pragma unroll
        for (int k = 0; k < 8; k++) {
            float4 x = hs4[k][j];
            acc[k] += wv.x * x.x + wv.y * x.y + wv.z * x.z + wv.w * x.w;
        }
    }
#pragma unroll
    for (int k = 0; k < 8; k++) acc[k] = warp_sum(acc[k]);
    if (lane == 0) {
        float bia = Wp_b[i];
        float vp  = vp_w[i];
#pragma unroll
        for (int k = 0; k < 8; k++) wtmp[w][k] = tanhf(acc[k] + bia) * vp;
    }
    __syncthreads();
    // reduce over 32 warps: warp k (k<8) sums wtmp[lane][k]
    if (w < 8) {
        float s = warp_sum(wtmp[lane][w]);
        if (lane == 0) g_pp[(b0 + w) * 32 + itile] = s;
    }
}

// ---------------------------------------------------------------------------
// k_q: 160 blocks.
//   [0,128): q partials. (e-tile 128) x (d-chunk 256) x (8 batches) -> g_qp4.
//   [128,160): c[b] = h[b]·Wa_b.
// ---------------------------------------------------------------------------
__global__ void __launch_bounds__(256) k_q(const float* __restrict__ h,
                    const float* __restrict__ Wa_w,
                    const float* __restrict__ Wa_b) {
    __shared__ float4 sbuf[2560];          // 40 KB
    int bid = blockIdx.x, t = threadIdx.x;
    if (bid < 128) {
        int et = bid & 7;                  // e-tile of 128 floats
        int dc = (bid >> 3) & 3;           // d-chunk of 256 rows
        int bg = bid >> 5;                 // 4 groups of 8 batches
        int b0 = bg * 8, d0 = dc * 256, e0 = et * 128;
        float*  hs  = (float*)sbuf;        // [8][256] = 8 KB
        float4* red = sbuf + 512;          // [8 dg][8 k][32 col] = 32 KB
        for (int idx = t; idx < 8 * 256; idx += 256) {
            int k = idx >> 8, d = idx & 255;
            hs[k * 256 + d] = h[(size_t)(b0 + k) * Dv + d0 + d];
        }
        __syncthreads();
        int col = t & 31, dg = t >> 5;     // 8 d-groups of 32 rows
        float4 acc[8];
#pragma unroll
        for (int k = 0; k < 8; k++) acc[k] = make_float4(0.f, 0.f, 0.f, 0.f);
#pragma unroll 4
        for (int i = 0; i < 32; i++) {
            int d = dg * 32 + i;
            float4 wv = ((const float4*)(Wa_w + (size_t)(d0 + d) * Ev + e0))[col];
#pragma unroll
            for (int k = 0; k < 8; k++) {
                float x = hs[k * 256 + d];
                acc[k].x += wv.x * x; acc[k].y += wv.y * x;
                acc[k].z += wv.z * x; acc[k].w += wv.w * x;
            }
        }
#pragma unroll
        for (int k = 0; k < 8; k++) red[(dg * 8 + k) * 32 + col] = acc[k];
        __syncthreads();
#pragma unroll
        for (int o = 4; o > 0; o >>= 1) {
            if (dg < o) {
#pragma unroll
                for (int k = 0; k < 8; k++) {
                    float4 u = red[(dg * 8 + k) * 32 + col];
                    float4 v = red[((dg + o) * 8 + k) * 32 + col];
                    u.x += v.x; u.y += v.y; u.z += v.z; u.w += v.w;
                    red[(dg * 8 + k) * 32 + col] = u;
                }
            }
            __syncthreads();
        }
        if (dg == 0) {
#pragma unroll
            for (int k = 0; k < 8; k++)
                ((float4*)(g_qp4[dc] + (size_t)(b0 + k) * Ev + e0))[col] =
                    red[k * 32 + col];
        }
    } else {
        int b = bid - 128;
        float v = 0.f;
        for (int d = t; d < Dv; d += 256) v += h[b * Dv + d] * Wa_b[d];
        v = warp_sum(v);
        __shared__ float redc[8];
        if ((t & 31) == 0) redc[t >> 5] = v;
        __syncthreads();
        if (t == 0) {
            float s = 0.f;
#pragma unroll
            for (int i = 0; i < 8; i++) s += redc[i];
            g_c[b] = s;
        }
    }
}

// ---------------------------------------------------------------------------
// k_att: grid (32 tiles, 32 batches), 256 threads. 4-partial q reduce; tile 0
// also finalizes p[b] (single warp). Then att for 64 s rows.
// ---------------------------------------------------------------------------
__global__ void __launch_bounds__(256) k_att(const float* __restrict__ enc,
                                             const float* __restrict__ vp_b) {
    __shared__ float4 qs[Ev / 4];
    int tile = blockIdx.x, b = blockIdx.y, t = threadIdx.x;

    {   // q = sum of 4 d-chunk partials: one float4 per thread
        float4 s0 = ((const float4*)(g_qp4[0] + b * Ev))[t];
        float4 s1 = ((const float4*)(g_qp4[1] + b * Ev))[t];
        float4 s2 = ((const float4*)(g_qp4[2] + b * Ev))[t];
        float4 s3 = ((const float4*)(g_qp4[3] + b * Ev))[t];
        float4 r;
        r.x = (s0.x + s1.x) + (s2.x + s3.x);
        r.y = (s0.y + s1.y) + (s2.y + s3.y);
        r.z = (s0.z + s1.z) + (s2.z + s3.z);
        r.w = (s0.w + s1.w) + (s2.w + s3.w);
        qs[t] = r;
    }
    // tile 0: finalize p[b] from 32 hp partials
    if (tile == 0 && t < 32) {
        float s = warp_sum(g_pp[b * 32 + t]);
        if (t == 0) {
            float x = s + vp_b[0];
            g_p[b] = (float)Sv / (1.f + expf(-x));
        }
    }
    __syncthreads();

    int w = t >> 5, lane = t & 31;
    float c = g_c[b];
#pragma unroll
    for (int r = 0; r < 8; r += 2) {
        int s = tile * 64 + w * 8 + r;
        const float4* er0 = (const float4*)(enc + ((size_t)b * Sv + s)     * Ev);
        const float4* er1 = (const float4*)(enc + ((size_t)b * Sv + s + 1) * Ev);
        float acc0 = 0.f, acc1 = 0.f;
#pragma unroll
        for (int j = lane; j < Ev / 4; j += 32) {
            float4 x  = qs[j];
            float4 a0 = __ldcs(er0 + j);
            float4 a1 = __ldcs(er1 + j);
            acc0 += a0.x * x.x + a0.y * x.y + a0.z * x.z + a0.w * x.w;
            acc1 += a1.x * x.x + a1.y * x.y + a1.z * x.z + a1.w * x.w;
        }
        acc0 = warp_sum(acc0);
        acc1 = warp_sum(acc1);
        if (lane == 0) {
            g_att[b * Sv + s]     = acc0 + c;
            g_att[b * Sv + s + 1] = acc1 + c;
        }
    }
}

// ---------------------------------------------------------------------------
// k_fin: grid (8 e-tiles, 32 batches), 1024 threads.
//   p is precomputed (g_p) -> enc window loads issue FIRST and stay in flight
//   under the softmax-stat computation. Tile 0 writes alpha; each block does
//   a 128-col slice of awe over the 64-row window (branchless; gauss is
//   exactly 0 outside, identical to the reference).
// ---------------------------------------------------------------------------
__global__ void k_fin(const float* __restrict__ enc, float* __restrict__ awe,
                      float* __restrict__ alpha) {
    int tile = blockIdx.x, b = blockIdx.y, t = threadIdx.x;
    int lane = t & 31, wrp = t >> 5;
    __shared__ float red[32];
    __shared__ float fin;
    __shared__ float aw[64];
    __shared__ float4 pacc[32][32];        // 16 KB

    float p = g_p[b];
    int lo = (int)floorf(p) - 31;
    if (lo < 0) lo = 0;
    if (lo > Sv - 64) lo = Sv - 64;

    // issue enc window loads early (hidden under softmax below)
    int col = t & 31;                      // float4 col within 128-col slice
    int rg  = t >> 5;                      // 32 row-groups of 2 rows
    const float4* base = (const float4*)(enc + ((size_t)b * Sv + lo) * Ev)
                         + tile * 32;
    float4 v0 = base[(size_t)(rg * 2)     * (Ev / 4) + col];
    float4 v1 = base[(size_t)(rg * 2 + 1) * (Ev / 4) + col];

    // softmax stats
    float a0 = g_att[b * Sv + t];
    float a1 = g_att[b * Sv + t + 1024];
    float m = warp_max(fmaxf(a0, a1));
    if (lane == 0) red[wrp] = m;
    __syncthreads();
    if (wrp == 0) {
        float v = warp_max(red[lane]);
        if (lane == 0) fin = v;
    }
    __syncthreads();
    float mb = fin;
    float e0 = expf(a0 - mb), e1 = expf(a1 - mb);
    float l = warp_sum(e0 + e1);
    __syncthreads();
    if (lane == 0) red[wrp] = l;
    __syncthreads();
    if (wrp == 0) {
        float v = warp_sum(red[lane]);
        if (lane == 0) fin = v;
    }
    __syncthreads();
    float inv = 1.f / fin;
    float d0 = (float)t - p, d1 = (float)(t + 1024) - p;
    float al0 = e0 * inv * expf(-d0 * d0 * 0.125f);
    float al1 = e1 * inv * expf(-d1 * d1 * 0.125f);
    if (tile == 0) {
        alpha[b * Sv + t]        = al0;
        alpha[b * Sv + t + 1024] = al1;
    }
    int w0 = t - lo, w1 = t + 1024 - lo;
    if ((unsigned)w0 < 64u) aw[w0] = al0;
    if ((unsigned)w1 < 64u) aw[w1] = al1;
    __syncthreads();

    // windowed awe slice: weights now available, loads already landed
    float aA = aw[rg * 2], aB = aw[rg * 2 + 1];
    float4 acc;
    acc.x = v0.x * aA + v1.x * aB;
    acc.y = v0.y * aA + v1.y * aB;
    acc.z = v0.z * aA + v1.z * aB;
    acc.w = v0.w * aA + v1.w * aB;
    pacc[rg][col] = acc;
    __syncthreads();
#pragma unroll
    for (int o = 16; o > 0; o >>= 1) {
        if (rg < o) {
            float4 u = pacc[rg][col], v = pacc[rg + o][col];
            u.x += v.x; u.y += v.y; u.z += v.z; u.w += v.w;
            pacc[rg][col] = u;
        }
        __syncthreads();
    }
    if (t < 32)
        ((float4*)(awe + b * Ev + tile * 128))[t] = pacc[0][t];
}

extern "C" void kernel_launch(void* const* d_in, const int* in_sizes, int n_in,
                              void* d_out, int out_size) {
    const float* enc  = (const float*)d_in[0];   // [B,S,E]
    const float* h    = (const float*)d_in[1];   // [B,D]
    const float* Wa_w = (const float*)d_in[3];   // [D,E]
    const float* Wa_b = (const float*)d_in[4];   // [D]
    const float* Wp_w = (const float*)d_in[5];   // [D,D]
    const float* Wp_b = (const float*)d_in[6];   // [D]
    const float* vp_w = (const float*)d_in[7];   // [1,D]
    const float* vp_b = (const float*)d_in[8];   // [1]

    float* awe   = (float*)d_out;                 // [B,E]
    float* alpha = (float*)d_out + Bv * Ev;       // [B,S]

    k_hp <<<128, 1024>>>(h, Wp_w, Wp_b, vp_w);
    k_q  <<<160, 256>>>(h, Wa_w, Wa_b);
    k_att<<<dim3(32, Bv), 256>>>(enc, vp_b);
    k_fin<<<dim3(8, Bv), 1024>>>(enc, awe, alpha);
}

// round 11
// speedup vs baseline: 1.0707x; 1.0310x over previous
#include <cuda_runtime.h>
#include <math.h>

#define Bv 32
#define Sv 2048
#define Ev 1024
#define Dv 1024

// Scratch (no device allocations)
__device__ float g_pp [Bv * 32];           // hp partials per (batch, itile32)
__device__ float g_qp4[4][Bv * Ev];        // q partials: 4 d-chunks
__device__ float g_c  [Bv];
__device__ float g_p  [Bv];
__device__ float g_att[Bv * Sv];
__device__ int   g_qcnt;                   // q/c blocks done (self-resetting)
__device__ int   g_pass;                   // att blocks past the spin

__device__ __forceinline__ float warp_sum(float v) {
#pragma unroll
    for (int o = 16; o > 0; o >>= 1) v += __shfl_xor_sync(0xffffffffu, v, o);
    return v;
}
__device__ __forceinline__ float warp_max(float v) {
#pragma unroll
    for (int o = 16; o > 0; o >>= 1) v = fmaxf(v, __shfl_xor_sync(0xffffffffu, v, o));
    return v;
}

// ---------------------------------------------------------------------------
// k_hp: 128 blocks x 1024 threads, single wave. Warp w of i-tile owns
// i = itile*32+w for 8 batches; cross-warp reduce -> g_pp (32 partials/batch).
// ---------------------------------------------------------------------------
__global__ void __launch_bounds__(1024) k_hp(const float* __restrict__ h,
                     const float* __restrict__ Wp_w,
                     const float* __restrict__ Wp_b,
                     const float* __restrict__ vp_w) {
    __shared__ float4 hs4[8][Dv / 4];     // 32 KB
    __shared__ float wtmp[32][8];         // [warp][batch]
    int t = threadIdx.x;
    int bg = blockIdx.x >> 5;
    int itile = blockIdx.x & 31;
    int b0 = bg * 8;
    {
        int idx = t;
        hs4[idx >> 8][idx & 255] = ((const float4*)(h + (size_t)(b0 + (idx >> 8)) * Dv))[idx & 255];
        idx = t + 1024;
        hs4[idx >> 8][idx & 255] = ((const float4*)(h + (size_t)(b0 + (idx >> 8)) * Dv))[idx & 255];
    }
    __syncthreads();
    int w = t >> 5, lane = t & 31;
    int i = itile * 32 + w;
    const float4* wr = (const float4*)(Wp_w + (size_t)i * Dv);
    float acc[8];
#pragma unroll
    for (int k = 0; k < 8; k++) acc[k] = 0.f;
#pragma unroll
    for (int j = lane; j < Dv / 4; j += 32) {
        float4 wv = wr[j];
#pragma unroll
        for (int k = 0; k < 8; k++) {
            float4 x = hs4[k][j];
            acc[k] += wv.x * x.x + wv.y * x.y + wv.z * x.z + wv.w * x.w;
        }
    }
#pragma unroll
    for (int k = 0; k < 8; k++) acc[k] = warp_sum(acc[k]);
    if (lane == 0) {
        float bia = Wp_b[i];
        float vp  = vp_w[i];
#pragma unroll
        for (int k = 0; k < 8; k++) wtmp[w][k] = tanhf(acc[k] + bia) * vp;
    }
    __syncthreads();
    if (w < 8) {
        float s = warp_sum(wtmp[lane][w]);
        if (lane == 0) g_pp[(b0 + w) * 32 + itile] = s;
    }
}

// ---------------------------------------------------------------------------
// k_attq: 1312 blocks x 256 threads, ONE node.
//   [0,256)    q partials: (e-tile 128) x (d-chunk 256) x (4 batches)
//   [256,288)  c[b] = h[b]·Wa_b
//   [288,1312) att: spin until qcnt==288, then 64 s rows per block.
//              tile 0 finalizes p[b] (g_pp from k_hp node).
// ---------------------------------------------------------------------------
__global__ void __launch_bounds__(256) k_attq(const float* __restrict__ enc,
                      const float* __restrict__ vp_b,
                      const float* __restrict__ h,
                      const float* __restrict__ Wa_w,
                      const float* __restrict__ Wa_b) {
    int bid = blockIdx.x, t = threadIdx.x;

    if (bid < 256) {
        // ---- q partial path ----
        __shared__ float  hs[4][256];      // 4 KB
        __shared__ float4 red[8 * 4 * 32]; // 16 KB
        int et = bid & 7;                  // e-tile of 128 floats
        int dc = (bid >> 3) & 3;           // d-chunk of 256 rows
        int bg = bid >> 5;                 // 8 groups of 4 batches
        int b0 = bg * 4, d0 = dc * 256, e0 = et * 128;
        for (int idx = t; idx < 4 * 256; idx += 256) {
            int k = idx >> 8, d = idx & 255;
            hs[k][d] = h[(size_t)(b0 + k) * Dv + d0 + d];
        }
        __syncthreads();
        int col = t & 31, dg = t >> 5;     // 8 d-groups of 32 rows
        float4 acc[4];
#pragma unroll
        for (int k = 0; k < 4; k++) acc[k] = make_float4(0.f, 0.f, 0.f, 0.f);
#pragma unroll 4
        for (int i = 0; i < 32; i++) {
            int d = dg * 32 + i;
            float4 wv = ((const float4*)(Wa_w + (size_t)(d0 + d) * Ev + e0))[col];
#pragma unroll
            for (int k = 0; k < 4; k++) {
                float x = hs[k][d];
                acc[k].x += wv.x * x; acc[k].y += wv.y * x;
                acc[k].z += wv.z * x; acc[k].w += wv.w * x;
            }
        }
#pragma unroll
        for (int k = 0; k < 4; k++) red[(dg * 4 + k) * 32 + col] = acc[k];
        __syncthreads();
#pragma unroll
        for (int o = 4; o > 0; o >>= 1) {
            if (dg < o) {
#pragma unroll
                for (int k = 0; k < 4; k++) {
                    float4 u = red[(dg * 4 + k) * 32 + col];
                    float4 v = red[((dg + o) * 4 + k) * 32 + col];
                    u.x += v.x; u.y += v.y; u.z += v.z; u.w += v.w;
                    red[(dg * 4 + k) * 32 + col] = u;
                }
            }
            __syncthreads();
        }
        if (dg == 0) {
#pragma unroll
            for (int k = 0; k < 4; k++)
                ((float4*)(g_qp4[dc] + (size_t)(b0 + k) * Ev + e0))[col] =
                    red[k * 32 + col];
        }
        __threadfence();
        __syncthreads();
        if (t == 0) atomicAdd(&g_qcnt, 1);
        return;
    }
    if (bid < 288) {
        // ---- c path ----
        int b = bid - 256;
        float v = 0.f;
        for (int d = t; d < Dv; d += 256) v += h[b * Dv + d] * Wa_b[d];
        v = warp_sum(v);
        __shared__ float redc[8];
        if ((t & 31) == 0) redc[t >> 5] = v;
        __syncthreads();
        if (t == 0) {
            float s = 0.f;
#pragma unroll
            for (int i = 0; i < 8; i++) s += redc[i];
            g_c[b] = s;
            __threadfence();
            atomicAdd(&g_qcnt, 1);
        }
        return;
    }

    // ---- att path ----
    int id = bid - 288;
    int tile = id & 31, b = id >> 5;

    // wait for q/c producers (wave-1 only; later blocks pass immediately)
    if (t == 0) {
        while (*(volatile int*)&g_qcnt < 288) {}
        // self-reset bookkeeping: the 1024th att block to pass resets both
        if (atomicAdd(&g_pass, 1) == 1023) { g_qcnt = 0; g_pass = 0; }
    }
    __syncthreads();
    __threadfence();

    __shared__ float4 qs[Ev / 4];
    {   // q = sum of 4 d-chunk partials
        float4 s0 = ((const float4*)(g_qp4[0] + b * Ev))[t];
        float4 s1 = ((const float4*)(g_qp4[1] + b * Ev))[t];
        float4 s2 = ((const float4*)(g_qp4[2] + b * Ev))[t];
        float4 s3 = ((const float4*)(g_qp4[3] + b * Ev))[t];
        float4 r;
        r.x = (s0.x + s1.x) + (s2.x + s3.x);
        r.y = (s0.y + s1.y) + (s2.y + s3.y);
        r.z = (s0.z + s1.z) + (s2.z + s3.z);
        r.w = (s0.w + s1.w) + (s2.w + s3.w);
        qs[t] = r;
    }
    // tile 0: finalize p[b] from 32 hp partials (k_hp node completed)
    if (tile == 0 && t < 32) {
        float s = warp_sum(g_pp[b * 32 + t]);
        if (t == 0) {
            float x = s + vp_b[0];
            g_p[b] = (float)Sv / (1.f + expf(-x));
        }
    }
    __syncthreads();

    int w = t >> 5, lane = t & 31;
    float c = g_c[b];
#pragma unroll
    for (int r = 0; r < 8; r += 2) {
        int s = tile * 64 + w * 8 + r;
        const float4* er0 = (const float4*)(enc + ((size_t)b * Sv + s)     * Ev);
        const float4* er1 = (const float4*)(enc + ((size_t)b * Sv + s + 1) * Ev);
        float acc0 = 0.f, acc1 = 0.f;
#pragma unroll
        for (int j = lane; j < Ev / 4; j += 32) {
            float4 x  = qs[j];
            float4 a0 = __ldcs(er0 + j);
            float4 a1 = __ldcs(er1 + j);
            acc0 += a0.x * x.x + a0.y * x.y + a0.z * x.z + a0.w * x.w;
            acc1 += a1.x * x.x + a1.y * x.y + a1.z * x.z + a1.w * x.w;
        }
        acc0 = warp_sum(acc0);
        acc1 = warp_sum(acc1);
        if (lane == 0) {
            g_att[b * Sv + s]     = acc0 + c;
            g_att[b * Sv + s + 1] = acc1 + c;
        }
    }
}

// ---------------------------------------------------------------------------
// k_fin: grid (8 e-tiles, 32 batches), 1024 threads. Enc window loads issue
// first (p precomputed) and stay in flight under the softmax stats.
// ---------------------------------------------------------------------------
__global__ void k_fin(const float* __restrict__ enc, float* __restrict__ awe,
                      float* __restrict__ alpha) {
    int tile = blockIdx.x, b = blockIdx.y, t = threadIdx.x;
    int lane = t & 31, wrp = t >> 5;
    __shared__ float red[32];
    __shared__ float fin;
    __shared__ float aw[64];
    __shared__ float4 pacc[32][32];        // 16 KB

    float p = g_p[b];
    int lo = (int)floorf(p) - 31;
    if (lo < 0) lo = 0;
    if (lo > Sv - 64) lo = Sv - 64;

    int col = t & 31;
    int rg  = t >> 5;
    const float4* base = (const float4*)(enc + ((size_t)b * Sv + lo) * Ev)
                         + tile * 32;
    float4 v0 = base[(size_t)(rg * 2)     * (Ev / 4) + col];
    float4 v1 = base[(size_t)(rg * 2 + 1) * (Ev / 4) + col];

    float a0 = g_att[b * Sv + t];
    float a1 = g_att[b * Sv + t + 1024];
    float m = warp_max(fmaxf(a0, a1));
    if (lane == 0) red[wrp] = m;
    __syncthreads();
    if (wrp == 0) {
        float v = warp_max(red[lane]);
        if (lane == 0) fin = v;
    }
    __syncthreads();
    float mb = fin;
    float e0 = expf(a0 - mb), e1 = expf(a1 - mb);
    float l = warp_sum(e0 + e1);
    __syncthreads();
    if (lane == 0) red[wrp] = l;
    __syncthreads();
    if (wrp == 0) {
        float v = warp_sum(red[lane]);
        if (lane == 0) fin = v;
    }
    __syncthreads();
    float inv = 1.f / fin;
    float d0 = (float)t - p, d1 = (float)(t + 1024) - p;
    float al0 = e0 * inv * expf(-d0 * d0 * 0.125f);
    float al1 = e1 * inv * expf(-d1 * d1 * 0.125f);
    if (tile == 0) {
        alpha[b * Sv + t]        = al0;
        alpha[b * Sv + t + 1024] = al1;
    }
    int w0 = t - lo, w1 = t + 1024 - lo;
    if ((unsigned)w0 < 64u) aw[w0] = al0;
    if ((unsigned)w1 < 64u) aw[w1] = al1;
    __syncthreads();

    float aA = aw[rg * 2], aB = aw[rg * 2 + 1];
    float4 acc;
    acc.x = v0.x * aA + v1.x * aB;
    acc.y = v0.y * aA + v1.y * aB;
    acc.z = v0.z * aA + v1.z * aB;
    acc.w = v0.w * aA + v1.w * aB;
    pacc[rg][col] = acc;
    __syncthreads();
#pragma unroll
    for (int o = 16; o > 0; o >>= 1) {
        if (rg < o) {
            float4 u = pacc[rg][col], v = pacc[rg + o][col];
            u.x += v.x; u.y += v.y; u.z += v.z; u.w += v.w;
            pacc[rg][col] = u;
        }
        __syncthreads();
    }
    if (t < 32)
        ((float4*)(awe + b * Ev + tile * 128))[t] = pacc[0][t];
}

extern "C" void kernel_launch(void* const* d_in, const int* in_sizes, int n_in,
                              void* d_out, int out_size) {
    const float* enc  = (const float*)d_in[0];   // [B,S,E]
    const float* h    = (const float*)d_in[1];   // [B,D]
    const float* Wa_w = (const float*)d_in[3];   // [D,E]
    const float* Wa_b = (const float*)d_in[4];   // [D]
    const float* Wp_w = (const float*)d_in[5];   // [D,D]
    const float* Wp_b = (const float*)d_in[6];   // [D]
    const float* vp_w = (const float*)d_in[7];   // [1,D]
    const float* vp_b = (const float*)d_in[8];   // [1]

    float* awe   = (float*)d_out;                 // [B,E]
    float* alpha = (float*)d_out + Bv * Ev;       // [B,S]

    k_hp  <<<128, 1024>>>(h, Wp_w, Wp_b, vp_w);
    k_attq<<<1312, 256>>>(enc, vp_b, h, Wa_w, Wa_b);
    k_fin <<<dim3(8, Bv), 1024>>>(enc, awe, alpha);
}

// round 12
// speedup vs baseline: 1.2170x; 1.1366x over previous
#include <cuda_runtime.h>
#include <math.h>

#define Bv 32
#define Sv 2048
#define Ev 1024
#define Dv 1024

// Scratch (no device allocations)
__device__ float g_pp [Bv * 128];          // hp partials per (batch, itile)
__device__ float g_qp4[4][Bv * Ev];        // q partials: 4 d-chunks
__device__ float g_c  [Bv];
__device__ float g_p  [Bv];
__device__ float g_att[Bv * Sv];
__device__ int   g_qcnt;                   // q/c producers done (self-reset)
__device__ int   g_pass;                   // att blocks past the spin
__device__ int   g_hcnt;                   // hp blocks done (self-reset)

__device__ __forceinline__ float warp_sum(float v) {
#pragma unroll
    for (int o = 16; o > 0; o >>= 1) v += __shfl_xor_sync(0xffffffffu, v, o);
    return v;
}
__device__ __forceinline__ float warp_max(float v) {
#pragma unroll
    for (int o = 16; o > 0; o >>= 1) v = fmaxf(v, __shfl_xor_sync(0xffffffffu, v, o));
    return v;
}

// ---------------------------------------------------------------------------
// k_main: 1824 blocks x 256 threads, ONE node.
//   [0,256)     q partials: (e-tile 128) x (d-chunk 256) x (4 batches)
//   [256,288)   c[b] = h[b]·Wa_b              (q+c signal g_qcnt)
//   [288,800)   hp partials -> g_pp; last one finalizes p[b] (g_hcnt)
//   [800,1824)  att: spin until g_qcnt==288, then 64 s rows per block.
//               hp does NOT gate att — it hides under att's DRAM phase.
// ---------------------------------------------------------------------------
__global__ void __launch_bounds__(256) k_main(const float* __restrict__ enc,
                      const float* __restrict__ vp_b,
                      const float* __restrict__ h,
                      const float* __restrict__ Wa_w,
                      const float* __restrict__ Wa_b,
                      const float* __restrict__ Wp_w,
                      const float* __restrict__ Wp_b,
                      const float* __restrict__ vp_w) {
    __shared__ float4 sbuf[2048];          // 32 KB, aliased by all paths
    int bid = blockIdx.x, t = threadIdx.x;

    if (bid < 256) {
        // ---- q partial path ----
        float*  hs  = (float*)sbuf;        // [4][256] = 4 KB
        float4* red = sbuf + 256;          // [8 dg][4 k][32 col] = 16 KB
        int et = bid & 7;                  // e-tile of 128 floats
        int dc = (bid >> 3) & 3;           // d-chunk of 256 rows
        int bg = bid >> 5;                 // 8 groups of 4 batches
        int b0 = bg * 4, d0 = dc * 256, e0 = et * 128;
        for (int idx = t; idx < 4 * 256; idx += 256) {
            int k = idx >> 8, d = idx & 255;
            hs[k * 256 + d] = h[(size_t)(b0 + k) * Dv + d0 + d];
        }
        __syncthreads();
        int col = t & 31, dg = t >> 5;
        float4 acc[4];
#pragma unroll
        for (int k = 0; k < 4; k++) acc[k] = make_float4(0.f, 0.f, 0.f, 0.f);
#pragma unroll 4
        for (int i = 0; i < 32; i++) {
            int d = dg * 32 + i;
            float4 wv = ((const float4*)(Wa_w + (size_t)(d0 + d) * Ev + e0))[col];
#pragma unroll
            for (int k = 0; k < 4; k++) {
                float x = hs[k * 256 + d];
                acc[k].x += wv.x * x; acc[k].y += wv.y * x;
                acc[k].z += wv.z * x; acc[k].w += wv.w * x;
            }
        }
#pragma unroll
        for (int k = 0; k < 4; k++) red[(dg * 4 + k) * 32 + col] = acc[k];
        __syncthreads();
#pragma unroll
        for (int o = 4; o > 0; o >>= 1) {
            if (dg < o) {
#pragma unroll
                for (int k = 0; k < 4; k++) {
                    float4 u = red[(dg * 4 + k) * 32 + col];
                    float4 v = red[((dg + o) * 4 + k) * 32 + col];
                    u.x += v.x; u.y += v.y; u.z += v.z; u.w += v.w;
                    red[(dg * 4 + k) * 32 + col] = u;
                }
            }
            __syncthreads();
        }
        if (dg == 0) {
#pragma unroll
            for (int k = 0; k < 4; k++)
                ((float4*)(g_qp4[dc] + (size_t)(b0 + k) * Ev + e0))[col] =
                    red[k * 32 + col];
        }
        __threadfence();
        __syncthreads();
        if (t == 0) atomicAdd(&g_qcnt, 1);
        return;
    }
    if (bid < 288) {
        // ---- c path ----
        int b = bid - 256;
        float v = 0.f;
        for (int d = t; d < Dv; d += 256) v += h[b * Dv + d] * Wa_b[d];
        v = warp_sum(v);
        __shared__ float redc[8];
        if ((t & 31) == 0) redc[t >> 5] = v;
        __syncthreads();
        if (t == 0) {
            float s = 0.f;
#pragma unroll
            for (int i = 0; i < 8; i++) s += redc[i];
            g_c[b] = s;
            __threadfence();
            atomicAdd(&g_qcnt, 1);
        }
        return;
    }
    if (bid < 800) {
        // ---- hp path: 8 i per block, 8 batches ----
        float4 (*hs4)[256] = (float4(*)[256])sbuf;   // 32 KB
        __shared__ float wtmp[8][8];
        int id = bid - 288;                // 0..511
        int b0 = (id >> 7) * 8;
        int itile = id & 127;
        for (int idx = t; idx < 8 * 256; idx += 256) {
            int k = idx >> 8, j = idx & 255;
            hs4[k][j] = ((const float4*)(h + (size_t)(b0 + k) * Dv))[j];
        }
        __syncthreads();
        int w = t >> 5, lane = t & 31;
        int i = itile * 8 + w;
        const float4* wr = (const float4*)(Wp_w + (size_t)i * Dv);
        float acc[8];
#pragma unroll
        for (int k = 0; k < 8; k++) acc[k] = 0.f;
#pragma unroll
        for (int j = lane; j < 256; j += 32) {
            float4 wv = wr[j];
#pragma unroll
            for (int k = 0; k < 8; k++) {
                float4 x = hs4[k][j];
                acc[k] += wv.x * x.x + wv.y * x.y + wv.z * x.z + wv.w * x.w;
            }
        }
#pragma unroll
        for (int k = 0; k < 8; k++) acc[k] = warp_sum(acc[k]);
        if (lane == 0) {
            float bia = Wp_b[i];
            float vp  = vp_w[i];
#pragma unroll
            for (int k = 0; k < 8; k++) wtmp[w][k] = tanhf(acc[k] + bia) * vp;
        }
        __syncthreads();
        if (t < 8) {
            float s = 0.f;
#pragma unroll
            for (int w2 = 0; w2 < 8; w2++) s += wtmp[w2][t];
            g_pp[(b0 + t) * 128 + itile] = s;
        }
        __threadfence();
        __syncthreads();
        __shared__ int hlast;
        if (t == 0) hlast = (atomicAdd(&g_hcnt, 1) == 511);
        __syncthreads();
        if (hlast) {
            __threadfence();
            // finalize p[b] for all 32 batches: 8 threads per batch
            int b = t >> 3, part = t & 7;
            float s = 0.f;
#pragma unroll
            for (int j = part; j < 128; j += 8) s += g_pp[b * 128 + j];
#pragma unroll
            for (int o = 4; o > 0; o >>= 1) s += __shfl_xor_sync(0xffffffffu, s, o);
            if (part == 0) {
                float x = s + vp_b[0];
                g_p[b] = (float)Sv / (1.f + expf(-x));
            }
            if (t == 0) g_hcnt = 0;        // reset for next replay
        }
        return;
    }

    // ---- att path ----
    int id = bid - 800;
    int tile = id & 31, b = id >> 5;

    if (t == 0) {
        while (*(volatile int*)&g_qcnt < 288) {}
        if (atomicAdd(&g_pass, 1) == 1023) { g_qcnt = 0; g_pass = 0; }
    }
    __syncthreads();
    __threadfence();

    float4* qs = sbuf;                     // 4 KB
    {   // q = sum of 4 d-chunk partials
        float4 s0 = ((const float4*)(g_qp4[0] + b * Ev))[t];
        float4 s1 = ((const float4*)(g_qp4[1] + b * Ev))[t];
        float4 s2 = ((const float4*)(g_qp4[2] + b * Ev))[t];
        float4 s3 = ((const float4*)(g_qp4[3] + b * Ev))[t];
        float4 r;
        r.x = (s0.x + s1.x) + (s2.x + s3.x);
        r.y = (s0.y + s1.y) + (s2.y + s3.y);
        r.z = (s0.z + s1.z) + (s2.z + s3.z);
        r.w = (s0.w + s1.w) + (s2.w + s3.w);
        qs[t] = r;
    }
    __syncthreads();

    int w = t >> 5, lane = t & 31;
    float c = g_c[b];
#pragma unroll
    for (int r = 0; r < 8; r += 2) {
        int s = tile * 64 + w * 8 + r;
        const float4* er0 = (const float4*)(enc + ((size_t)b * Sv + s)     * Ev);
        const float4* er1 = (const float4*)(enc + ((size_t)b * Sv + s + 1) * Ev);
        float acc0 = 0.f, acc1 = 0.f;
#pragma unroll
        for (int j = lane; j < Ev / 4; j += 32) {
            float4 x  = qs[j];
            float4 a0 = __ldcs(er0 + j);
            float4 a1 = __ldcs(er1 + j);
            acc0 += a0.x * x.x + a0.y * x.y + a0.z * x.z + a0.w * x.w;
            acc1 += a1.x * x.x + a1.y * x.y + a1.z * x.z + a1.w * x.w;
        }
        acc0 = warp_sum(acc0);
        acc1 = warp_sum(acc1);
        if (lane == 0) {
            g_att[b * Sv + s]     = acc0 + c;
            g_att[b * Sv + s + 1] = acc1 + c;
        }
    }
}

// ---------------------------------------------------------------------------
// k_fin: grid (8 e-tiles, 32 batches), 1024 threads. p precomputed -> enc
// window loads issue first and stay in flight under the softmax stats.
// ---------------------------------------------------------------------------
__global__ void k_fin(const float* __restrict__ enc, float* __restrict__ awe,
                      float* __restrict__ alpha) {
    int tile = blockIdx.x, b = blockIdx.y, t = threadIdx.x;
    int lane = t & 31, wrp = t >> 5;
    __shared__ float red[32];
    __shared__ float fin;
    __shared__ float aw[64];
    __shared__ float4 pacc[32][32];        // 16 KB

    float p = g_p[b];
    int lo = (int)floorf(p) - 31;
    if (lo < 0) lo = 0;
    if (lo > Sv - 64) lo = Sv - 64;

    int col = t & 31;
    int rg  = t >> 5;
    const float4* base = (const float4*)(enc + ((size_t)b * Sv + lo) * Ev)
                         + tile * 32;
    float4 v0 = base[(size_t)(rg * 2)     * (Ev / 4) + col];
    float4 v1 = base[(size_t)(rg * 2 + 1) * (Ev / 4) + col];

    float a0 = g_att[b * Sv + t];
    float a1 = g_att[b * Sv + t + 1024];
    float m = warp_max(fmaxf(a0, a1));
    if (lane == 0) red[wrp] = m;
    __syncthreads();
    if (wrp == 0) {
        float v = warp_max(red[lane]);
        if (lane == 0) fin = v;
    }
    __syncthreads();
    float mb = fin;
    float e0 = expf(a0 - mb), e1 = expf(a1 - mb);
    float l = warp_sum(e0 + e1);
    __syncthreads();
    if (lane == 0) red[wrp] = l;
    __syncthreads();
    if (wrp == 0) {
        float v = warp_sum(red[lane]);
        if (lane == 0) fin = v;
    }
    __syncthreads();
    float inv = 1.f / fin;
    float d0 = (float)t - p, d1 = (float)(t + 1024) - p;
    float al0 = e0 * inv * expf(-d0 * d0 * 0.125f);
    float al1 = e1 * inv * expf(-d1 * d1 * 0.125f);
    if (tile == 0) {
        alpha[b * Sv + t]        = al0;
        alpha[b * Sv + t + 1024] = al1;
    }
    int w0 = t - lo, w1 = t + 1024 - lo;
    if ((unsigned)w0 < 64u) aw[w0] = al0;
    if ((unsigned)w1 < 64u) aw[w1] = al1;
    __syncthreads();

    float aA = aw[rg * 2], aB = aw[rg * 2 + 1];
    float4 acc;
    acc.x = v0.x * aA + v1.x * aB;
    acc.y = v0.y * aA + v1.y * aB;
    acc.z = v0.z * aA + v1.z * aB;
    acc.w = v0.w * aA + v1.w * aB;
    pacc[rg][col] = acc;
    __syncthreads();
#pragma unroll
    for (int o = 16; o > 0; o >>= 1) {
        if (rg < o) {
            float4 u = pacc[rg][col], v = pacc[rg + o][col];
            u.x += v.x; u.y += v.y; u.z += v.z; u.w += v.w;
            pacc[rg][col] = u;
        }
        __syncthreads();
    }
    if (t < 32)
        ((float4*)(awe + b * Ev + tile * 128))[t] = pacc[0][t];
}

extern "C" void kernel_launch(void* const* d_in, const int* in_sizes, int n_in,
                              void* d_out, int out_size) {
    const float* enc  = (const float*)d_in[0];   // [B,S,E]
    const float* h    = (const float*)d_in[1];   // [B,D]
    const float* Wa_w = (const float*)d_in[3];   // [D,E]
    const float* Wa_b = (const float*)d_in[4];   // [D]
    const float* Wp_w = (const float*)d_in[5];   // [D,D]
    const float* Wp_b = (const float*)d_in[6];   // [D]
    const float* vp_w = (const float*)d_in[7];   // [1,D]
    const float* vp_b = (const float*)d_in[8];   // [1]

    float* awe   = (float*)d_out;                 // [B,E]
    float* alpha = (float*)d_out + Bv * Ev;       // [B,S]

    k_main<<<1824, 256>>>(enc, vp_b, h, Wa_w, Wa_b, Wp_w, Wp_b, vp_w);
    k_fin <<<dim3(8, Bv), 1024>>>(enc, awe, alpha);
}